// round 1
// baseline (speedup 1.0000x reference)
#include <cuda_runtime.h>
#include <math.h>

// Problem dims (fixed)
#define B_  8
#define M_  1024
#define H_  1024
#define NH_ 16
#define HD_ 64
#define ROWS 8192        // B*M
#define H1W 256

// Output layout: z [8,1024], attn [8,16,1024,1024], sigma [8,1024]
#define Z_OFF     ((size_t)0)
#define ATTN_OFF  ((size_t)8192)
#define SIGMA_OFF ((size_t)8192 + (size_t)B_*NH_*M_*M_)

// -------- scratch (device globals; no allocation allowed) --------
__device__ float g_q[ROWS*H_];
__device__ float g_k[ROWS*H_];
__device__ float g_v[ROWS*H_];
__device__ float g_gate[ROWS*H_];
__device__ float g_h1[ROWS*H1W];
__device__ float g_sigma[ROWS];
__device__ float g_part[B_*NH_*32*HD_];   // per (b,h,mtile) partial column means

// ============================================================
// Kernel 1: fused projection GEMM
// C[8192, 4352] = X[8192,1024] @ [Wq|Wk|Wv|Wg|Wu1] + bias, with per-section
// activation (none/none/none/sigmoid/relu), scattered to scratch buffers.
// 128x128 tile, k-chunk 8, 256 threads, 8x8 microtile.
// ============================================================
__global__ __launch_bounds__(256) void proj_kernel(
    const float* __restrict__ X,
    const float* __restrict__ Wq, const float* __restrict__ bq,
    const float* __restrict__ Wk, const float* __restrict__ bk,
    const float* __restrict__ Wv, const float* __restrict__ bv,
    const float* __restrict__ Wg, const float* __restrict__ bg,
    const float* __restrict__ Wu1, const float* __restrict__ bu1)
{
    __shared__ float Xs[8][128];
    __shared__ float Ws[8][128];

    const int rowt = blockIdx.x * 128;
    const int colt = blockIdx.y * 128;

    const float* W; const float* bias; float* out;
    int wld, outld, lcol, act;
    if (colt < 1024)      { W=Wq;  bias=bq;  out=g_q;    wld=1024; outld=1024; lcol=colt;      act=0; }
    else if (colt < 2048) { W=Wk;  bias=bk;  out=g_k;    wld=1024; outld=1024; lcol=colt-1024; act=0; }
    else if (colt < 3072) { W=Wv;  bias=bv;  out=g_v;    wld=1024; outld=1024; lcol=colt-2048; act=0; }
    else if (colt < 4096) { W=Wg;  bias=bg;  out=g_gate; wld=1024; outld=1024; lcol=colt-3072; act=1; }
    else                  { W=Wu1; bias=bu1; out=g_h1;   wld=256;  outld=256;  lcol=colt-4096; act=2; }

    const int tid  = threadIdx.x;
    const int row0 = (tid >> 4) << 3;   // 0..120
    const int col0 = (tid & 15) << 3;   // 0..120

    float acc[8][8];
#pragma unroll
    for (int i = 0; i < 8; i++)
#pragma unroll
        for (int j = 0; j < 8; j++) acc[i][j] = 0.f;

    const int xr = tid >> 1;            // 0..127
    const int xk = (tid & 1) << 2;      // 0 or 4
    const int wk = tid >> 5;            // 0..7
    const int wc = (tid & 31) << 2;     // 0..124

    for (int k0 = 0; k0 < 1024; k0 += 8) {
        float4 xv = *(const float4*)&X[(size_t)(rowt + xr)*1024 + k0 + xk];
        Xs[xk+0][xr] = xv.x; Xs[xk+1][xr] = xv.y;
        Xs[xk+2][xr] = xv.z; Xs[xk+3][xr] = xv.w;
        float4 wv = *(const float4*)&W[(size_t)(k0 + wk)*wld + lcol + wc];
        *(float4*)&Ws[wk][wc] = wv;
        __syncthreads();
#pragma unroll
        for (int kk = 0; kk < 8; kk++) {
            float a[8], bb[8];
            *(float4*)&a[0]  = *(const float4*)&Xs[kk][row0];
            *(float4*)&a[4]  = *(const float4*)&Xs[kk][row0+4];
            *(float4*)&bb[0] = *(const float4*)&Ws[kk][col0];
            *(float4*)&bb[4] = *(const float4*)&Ws[kk][col0+4];
#pragma unroll
            for (int i = 0; i < 8; i++)
#pragma unroll
                for (int j = 0; j < 8; j++)
                    acc[i][j] += a[i] * bb[j];
        }
        __syncthreads();
    }

    float bv8[8];
#pragma unroll
    for (int j = 0; j < 8; j++) bv8[j] = bias[lcol + col0 + j];

#pragma unroll
    for (int i = 0; i < 8; i++) {
        const int gr = rowt + row0 + i;
        float o[8];
#pragma unroll
        for (int j = 0; j < 8; j++) {
            float c = acc[i][j] + bv8[j];
            if (act == 1)      c = 1.f / (1.f + __expf(-c));
            else if (act == 2) c = fmaxf(c, 0.f);
            o[j] = c;
        }
        *(float4*)&out[(size_t)gr*outld + lcol + col0]     = *(float4*)&o[0];
        *(float4*)&out[(size_t)gr*outld + lcol + col0 + 4] = *(float4*)&o[4];
    }
}

// ============================================================
// Kernel 2: sigma = softplus(h1 @ Wu2 + bu2) + 1e-6  (one warp per row)
// ============================================================
__global__ __launch_bounds__(256) void sigma_kernel(
    const float* __restrict__ Wu2, const float* __restrict__ bu2,
    float* __restrict__ out)
{
    const int tid  = threadIdx.x;
    const int w    = tid >> 5, lane = tid & 31;
    const int row  = blockIdx.x * 8 + w;

    const float* hr = &g_h1[(size_t)row * H1W];
    float s = 0.f;
#pragma unroll
    for (int j = lane; j < H1W; j += 32) s += hr[j] * Wu2[j];
#pragma unroll
    for (int o = 16; o; o >>= 1) s += __shfl_xor_sync(0xFFFFFFFFu, s, o);
    if (lane == 0) {
        float v  = s + bu2[0];
        float sp = (v > 15.f) ? v : log1pf(__expf(v));
        float sg = sp + 1e-6f;
        g_sigma[row] = sg;
        out[SIGMA_OFF + row] = sg;
    }
}

// ============================================================
// Kernel 3: attention per (mtile=32, head, batch)
// Single pass: exp(scores) buffered in smem (32x1024 fp32), row sums,
// attn written normalized, ctx = P@V normalized + gated, partial column
// means written (no atomics).
// ============================================================
#define P_LD   1028
#define QS_LD  36
#define KS_LD  132
#define VS_LD  68
#define SM_P    0
#define SM_QS  (SM_P  + 32*P_LD)          // 32896
#define SM_KV  (SM_QS + 64*QS_LD)         // 35200
#define SM_ISN (SM_KV + 8704)             // 43904
#define SM_SCL (SM_ISN + 1024)            // 44928
#define SM_INVL (SM_SCL + 32)             // 44960
#define SM_CS  (SM_INVL + 32)             // 44992
#define SM_TOT (SM_CS + 32*VS_LD)         // 47168 floats = 188672 bytes
#define ATTN_SMEM_BYTES (SM_TOT * 4)

__global__ __launch_bounds__(256) void attn_kernel(float* __restrict__ out)
{
    extern __shared__ float sm[];
    float* P    = sm + SM_P;
    float* Qs   = sm + SM_QS;
    float* KV   = sm + SM_KV;
    float* isn  = sm + SM_ISN;
    float* scl  = sm + SM_SCL;
    float* invl = sm + SM_INVL;
    float* Cs   = sm + SM_CS;

    const int mt = blockIdx.x, h = blockIdx.y, b = blockIdx.z;
    const int m0 = mt * 32;
    const int tid = threadIdx.x;

    // sigma terms
    for (int n = tid; n < 1024; n += 256) isn[n] = 1.f / g_sigma[(b << 10) + n];
    if (tid < 32) scl[tid] = 0.125f / g_sigma[(b << 10) + m0 + tid];   // 1/sqrt(64)=0.125

    // Q tile, d-major
    for (int e = tid; e < 32*64; e += 256) {
        int i = e >> 6, d = e & 63;
        Qs[d*QS_LD + i] = g_q[((size_t)(b << 10) + m0 + i)*1024 + (h << 6) + d];
    }
    __syncthreads();

    // ---- QK^T, exp, store to P ----
    const int i0 = (tid >> 5) << 2;    // 4 rows per warp
    const int j0 = (tid & 31) << 2;    // 4 cols per lane
    for (int c = 0; c < 8; c++) {
        const int n0 = c * 128;
        for (int e = tid; e < 128*64; e += 256) {
            int j = e >> 6, d = e & 63;
            KV[d*KS_LD + j] = g_k[((size_t)(b << 10) + n0 + j)*1024 + (h << 6) + d];
        }
        __syncthreads();

        float acc[4][4];
#pragma unroll
        for (int ii = 0; ii < 4; ii++)
#pragma unroll
            for (int jj = 0; jj < 4; jj++) acc[ii][jj] = 0.f;

#pragma unroll 8
        for (int d = 0; d < 64; d++) {
            float4 a  = *(const float4*)&Qs[d*QS_LD + i0];
            float4 bb = *(const float4*)&KV[d*KS_LD + j0];
            float av[4] = {a.x, a.y, a.z, a.w};
            float bv[4] = {bb.x, bb.y, bb.z, bb.w};
#pragma unroll
            for (int ii = 0; ii < 4; ii++)
#pragma unroll
                for (int jj = 0; jj < 4; jj++)
                    acc[ii][jj] += av[ii] * bv[jj];
        }
#pragma unroll
        for (int ii = 0; ii < 4; ii++) {
            float smv = scl[i0 + ii];
#pragma unroll
            for (int jj = 0; jj < 4; jj++) {
                float s = acc[ii][jj] * smv * isn[n0 + j0 + jj];
                P[(i0 + ii)*P_LD + n0 + j0 + jj] = __expf(s);
            }
        }
        __syncthreads();
    }

    // ---- row sums -> 1/l ----
    {
        const int w = tid >> 5, lane = tid & 31;
#pragma unroll
        for (int r = w*4; r < w*4 + 4; r++) {
            float s = 0.f;
            for (int n = lane; n < 1024; n += 32) s += P[r*P_LD + n];
#pragma unroll
            for (int o = 16; o; o >>= 1) s += __shfl_xor_sync(0xFFFFFFFFu, s, o);
            if (lane == 0) invl[r] = 1.f / s;
        }
    }
    __syncthreads();

    // ---- write normalized attn ----
    {
        const size_t base = ATTN_OFF + (((size_t)(b*16 + h))*1024 + m0)*1024;
        for (int e = tid; e < 32*1024; e += 256) {
            int i = e >> 10, n = e & 1023;
            out[base + (size_t)i*1024 + n] = P[i*P_LD + n] * invl[i];
        }
    }

    // ---- ctx = P @ V ----
    const int d0  = (tid & 15) << 2;   // 4 dims
    const int i0b = (tid >> 4) << 1;   // 2 rows
    float cacc[2][4];
#pragma unroll
    for (int ii = 0; ii < 2; ii++)
#pragma unroll
        for (int dd = 0; dd < 4; dd++) cacc[ii][dd] = 0.f;

    for (int c = 0; c < 8; c++) {
        const int n0 = c * 128;
        __syncthreads();  // previous chunk compute done before KV overwrite
        for (int e = tid; e < 128*64; e += 256) {
            int j = e >> 6, d = e & 63;
            KV[j*VS_LD + d] = g_v[((size_t)(b << 10) + n0 + j)*1024 + (h << 6) + d];
        }
        __syncthreads();
#pragma unroll 4
        for (int j = 0; j < 128; j++) {
            float p0 = P[i0b*P_LD + n0 + j];
            float p1 = P[(i0b + 1)*P_LD + n0 + j];
            float4 vv = *(const float4*)&KV[j*VS_LD + d0];
            cacc[0][0] += p0*vv.x; cacc[0][1] += p0*vv.y;
            cacc[0][2] += p0*vv.z; cacc[0][3] += p0*vv.w;
            cacc[1][0] += p1*vv.x; cacc[1][1] += p1*vv.y;
            cacc[1][2] += p1*vv.z; cacc[1][3] += p1*vv.w;
        }
    }
    __syncthreads();

    // ---- gate, store partial column means ----
#pragma unroll
    for (int ii = 0; ii < 2; ii++) {
        const int i = i0b + ii;
#pragma unroll
        for (int dd = 0; dd < 4; dd++) {
            const int d = d0 + dd;
            float g = g_gate[((size_t)(b << 10) + m0 + i)*1024 + (h << 6) + d];
            Cs[i*VS_LD + d] = cacc[ii][dd] * invl[i] * g;
        }
    }
    __syncthreads();
    if (tid < 64) {
        float s = 0.f;
#pragma unroll
        for (int i = 0; i < 32; i++) s += Cs[i*VS_LD + tid];
        g_part[(((b << 4) + h)*32 + mt)*64 + tid] = s * (1.f/1024.f);
    }
}

// ============================================================
// Kernel 4: z = colmean @ Wo + bo
// ============================================================
__global__ __launch_bounds__(256) void z_kernel(
    const float* __restrict__ Wo, const float* __restrict__ bo,
    float* __restrict__ out)
{
    __shared__ float cm[1024];
    const int b = blockIdx.x;
    const int o = blockIdx.y*256 + threadIdx.x;

    for (int c = threadIdx.x; c < 1024; c += 256) {
        int hh = c >> 6, d = c & 63;
        const float* pp = &g_part[(((b << 4) + hh)*32)*64 + d];
        float s = 0.f;
#pragma unroll
        for (int t = 0; t < 32; t++) s += pp[t*64];
        cm[c] = s;
    }
    __syncthreads();

    float acc = bo[o];
#pragma unroll 4
    for (int c = 0; c < 1024; c++) acc += cm[c] * Wo[(size_t)c*1024 + o];
    out[Z_OFF + (size_t)b*1024 + o] = acc;
}

// ============================================================
extern "C" void kernel_launch(void* const* d_in, const int* in_sizes, int n_in,
                              void* d_out, int out_size)
{
    const float* x   = (const float*)d_in[0];
    const float* Wq  = (const float*)d_in[1];
    const float* bq  = (const float*)d_in[2];
    const float* Wk  = (const float*)d_in[3];
    const float* bk  = (const float*)d_in[4];
    const float* Wv  = (const float*)d_in[5];
    const float* bv  = (const float*)d_in[6];
    const float* Wg  = (const float*)d_in[7];
    const float* bg  = (const float*)d_in[8];
    const float* Wo  = (const float*)d_in[9];
    const float* bo  = (const float*)d_in[10];
    const float* Wu1 = (const float*)d_in[11];
    const float* bu1 = (const float*)d_in[12];
    const float* Wu2 = (const float*)d_in[13];
    const float* bu2 = (const float*)d_in[14];
    float* out = (float*)d_out;

    proj_kernel<<<dim3(64, 34), 256>>>(x, Wq, bq, Wk, bk, Wv, bv, Wg, bg, Wu1, bu1);
    sigma_kernel<<<1024, 256>>>(Wu2, bu2, out);
    cudaFuncSetAttribute(attn_kernel, cudaFuncAttributeMaxDynamicSharedMemorySize,
                         ATTN_SMEM_BYTES);
    attn_kernel<<<dim3(32, 16, 8), 256, ATTN_SMEM_BYTES>>>(out);
    z_kernel<<<dim3(8, 4), 256>>>(Wo, bo, out);
}

// round 2
// speedup vs baseline: 1.4587x; 1.4587x over previous
#include <cuda_runtime.h>
#include <math.h>

// Problem dims (fixed)
#define B_  8
#define M_  1024
#define H_  1024
#define NH_ 16
#define HD_ 64
#define ROWS 8192        // B*M
#define H1W 256

// Output layout: z [8,1024], attn [8,16,1024,1024], sigma [8,1024]
#define Z_OFF     ((size_t)0)
#define ATTN_OFF  ((size_t)8192)
#define SIGMA_OFF ((size_t)8192 + (size_t)B_*NH_*M_*M_)

// -------- scratch (device globals; no allocation allowed) --------
__device__ float g_q[ROWS*H_];
__device__ float g_k[ROWS*H_];
__device__ float g_v[ROWS*H_];
__device__ float g_gate[ROWS*H_];
__device__ float g_h1[ROWS*H1W];
__device__ float g_sigma[ROWS];
__device__ float g_part[B_*NH_*32*HD_];   // per (b,h,mtile) partial column means

// ============================================================
// Kernel 1: fused projection GEMM
// C[8192, 4352] = X[8192,1024] @ [Wq|Wk|Wv|Wg|Wu1] + bias, with per-section
// activation (none/none/none/sigmoid/relu), scattered to scratch buffers.
// 128x128 tile, k-chunk 8, 256 threads, 8x8 microtile.
// ============================================================
__global__ __launch_bounds__(256) void proj_kernel(
    const float* __restrict__ X,
    const float* __restrict__ Wq, const float* __restrict__ bq,
    const float* __restrict__ Wk, const float* __restrict__ bk,
    const float* __restrict__ Wv, const float* __restrict__ bv,
    const float* __restrict__ Wg, const float* __restrict__ bg,
    const float* __restrict__ Wu1, const float* __restrict__ bu1)
{
    __shared__ float Xs[8][128];
    __shared__ float Ws[8][128];

    const int rowt = blockIdx.x * 128;
    const int colt = blockIdx.y * 128;

    const float* W; const float* bias; float* out;
    int wld, outld, lcol, act;
    if (colt < 1024)      { W=Wq;  bias=bq;  out=g_q;    wld=1024; outld=1024; lcol=colt;      act=0; }
    else if (colt < 2048) { W=Wk;  bias=bk;  out=g_k;    wld=1024; outld=1024; lcol=colt-1024; act=0; }
    else if (colt < 3072) { W=Wv;  bias=bv;  out=g_v;    wld=1024; outld=1024; lcol=colt-2048; act=0; }
    else if (colt < 4096) { W=Wg;  bias=bg;  out=g_gate; wld=1024; outld=1024; lcol=colt-3072; act=1; }
    else                  { W=Wu1; bias=bu1; out=g_h1;   wld=256;  outld=256;  lcol=colt-4096; act=2; }

    const int tid  = threadIdx.x;
    const int row0 = (tid >> 4) << 3;   // 0..120
    const int col0 = (tid & 15) << 3;   // 0..120

    float acc[8][8];
#pragma unroll
    for (int i = 0; i < 8; i++)
#pragma unroll
        for (int j = 0; j < 8; j++) acc[i][j] = 0.f;

    const int xr = tid >> 1;            // 0..127
    const int xk = (tid & 1) << 2;      // 0 or 4
    const int wk = tid >> 5;            // 0..7
    const int wc = (tid & 31) << 2;     // 0..124

    for (int k0 = 0; k0 < 1024; k0 += 8) {
        float4 xv = *(const float4*)&X[(size_t)(rowt + xr)*1024 + k0 + xk];
        Xs[xk+0][xr] = xv.x; Xs[xk+1][xr] = xv.y;
        Xs[xk+2][xr] = xv.z; Xs[xk+3][xr] = xv.w;
        float4 wv = *(const float4*)&W[(size_t)(k0 + wk)*wld + lcol + wc];
        *(float4*)&Ws[wk][wc] = wv;
        __syncthreads();
#pragma unroll
        for (int kk = 0; kk < 8; kk++) {
            float a[8], bb[8];
            *(float4*)&a[0]  = *(const float4*)&Xs[kk][row0];
            *(float4*)&a[4]  = *(const float4*)&Xs[kk][row0+4];
            *(float4*)&bb[0] = *(const float4*)&Ws[kk][col0];
            *(float4*)&bb[4] = *(const float4*)&Ws[kk][col0+4];
#pragma unroll
            for (int i = 0; i < 8; i++)
#pragma unroll
                for (int j = 0; j < 8; j++)
                    acc[i][j] += a[i] * bb[j];
        }
        __syncthreads();
    }

    float bv8[8];
#pragma unroll
    for (int j = 0; j < 8; j++) bv8[j] = bias[lcol + col0 + j];

#pragma unroll
    for (int i = 0; i < 8; i++) {
        const int gr = rowt + row0 + i;
        float o[8];
#pragma unroll
        for (int j = 0; j < 8; j++) {
            float c = acc[i][j] + bv8[j];
            if (act == 1)      c = 1.f / (1.f + __expf(-c));
            else if (act == 2) c = fmaxf(c, 0.f);
            o[j] = c;
        }
        *(float4*)&out[(size_t)gr*outld + lcol + col0]     = *(float4*)&o[0];
        *(float4*)&out[(size_t)gr*outld + lcol + col0 + 4] = *(float4*)&o[4];
    }
}

// ============================================================
// Kernel 2: sigma = softplus(h1 @ Wu2 + bu2) + 1e-6  (one warp per row)
// ============================================================
__global__ __launch_bounds__(256) void sigma_kernel(
    const float* __restrict__ Wu2, const float* __restrict__ bu2,
    float* __restrict__ out)
{
    const int tid  = threadIdx.x;
    const int w    = tid >> 5, lane = tid & 31;
    const int row  = blockIdx.x * 8 + w;

    const float* hr = &g_h1[(size_t)row * H1W];
    float s = 0.f;
#pragma unroll
    for (int j = lane; j < H1W; j += 32) s += hr[j] * Wu2[j];
#pragma unroll
    for (int o = 16; o; o >>= 1) s += __shfl_xor_sync(0xFFFFFFFFu, s, o);
    if (lane == 0) {
        float v  = s + bu2[0];
        float sp = (v > 15.f) ? v : log1pf(__expf(v));
        float sg = sp + 1e-6f;
        g_sigma[row] = sg;
        out[SIGMA_OFF + row] = sg;
    }
}

// ============================================================
// Kernel 3: attention per (mtile=32, head, batch)
// Single pass: exp(scores) buffered in smem (32x1024 fp32), row sums,
// attn written normalized, ctx = P@V normalized + gated, partial column
// means written (no atomics).
// ============================================================
#define P_LD   1028
#define QS_LD  36
#define KS_LD  132
#define VS_LD  68
#define SM_P    0
#define SM_QS  (SM_P  + 32*P_LD)          // 32896
#define SM_KV  (SM_QS + 64*QS_LD)         // 35200
#define SM_ISN (SM_KV + 8704)             // 43904
#define SM_SCL (SM_ISN + 1024)            // 44928
#define SM_INVL (SM_SCL + 32)             // 44960
#define SM_CS  (SM_INVL + 32)             // 44992
#define SM_TOT (SM_CS + 32*VS_LD)         // 47168 floats = 188672 bytes
#define ATTN_SMEM_BYTES (SM_TOT * 4)

__global__ __launch_bounds__(256) void attn_kernel(float* __restrict__ out)
{
    extern __shared__ float sm[];
    float* P    = sm + SM_P;
    float* Qs   = sm + SM_QS;
    float* KV   = sm + SM_KV;
    float* isn  = sm + SM_ISN;
    float* scl  = sm + SM_SCL;
    float* invl = sm + SM_INVL;
    float* Cs   = sm + SM_CS;

    const int mt = blockIdx.x, h = blockIdx.y, b = blockIdx.z;
    const int m0 = mt * 32;
    const int tid = threadIdx.x;

    // sigma terms
    for (int n = tid; n < 1024; n += 256) isn[n] = 1.f / g_sigma[(b << 10) + n];
    if (tid < 32) scl[tid] = 0.125f / g_sigma[(b << 10) + m0 + tid];   // 1/sqrt(64)=0.125

    // Q tile, d-major
    for (int e = tid; e < 32*64; e += 256) {
        int i = e >> 6, d = e & 63;
        Qs[d*QS_LD + i] = g_q[((size_t)(b << 10) + m0 + i)*1024 + (h << 6) + d];
    }
    __syncthreads();

    // ---- QK^T, exp, store to P ----
    const int i0 = (tid >> 5) << 2;    // 4 rows per warp
    const int j0 = (tid & 31) << 2;    // 4 cols per lane
    for (int c = 0; c < 8; c++) {
        const int n0 = c * 128;
        for (int e = tid; e < 128*64; e += 256) {
            int j = e >> 6, d = e & 63;
            KV[d*KS_LD + j] = g_k[((size_t)(b << 10) + n0 + j)*1024 + (h << 6) + d];
        }
        __syncthreads();

        float acc[4][4];
#pragma unroll
        for (int ii = 0; ii < 4; ii++)
#pragma unroll
            for (int jj = 0; jj < 4; jj++) acc[ii][jj] = 0.f;

#pragma unroll 8
        for (int d = 0; d < 64; d++) {
            float4 a  = *(const float4*)&Qs[d*QS_LD + i0];
            float4 bb = *(const float4*)&KV[d*KS_LD + j0];
            float av[4] = {a.x, a.y, a.z, a.w};
            float bv[4] = {bb.x, bb.y, bb.z, bb.w};
#pragma unroll
            for (int ii = 0; ii < 4; ii++)
#pragma unroll
                for (int jj = 0; jj < 4; jj++)
                    acc[ii][jj] += av[ii] * bv[jj];
        }
#pragma unroll
        for (int ii = 0; ii < 4; ii++) {
            float smv = scl[i0 + ii];
#pragma unroll
            for (int jj = 0; jj < 4; jj++) {
                float s = acc[ii][jj] * smv * isn[n0 + j0 + jj];
                P[(i0 + ii)*P_LD + n0 + j0 + jj] = __expf(s);
            }
        }
        __syncthreads();
    }

    // ---- row sums -> 1/l ----
    {
        const int w = tid >> 5, lane = tid & 31;
#pragma unroll
        for (int r = w*4; r < w*4 + 4; r++) {
            float s = 0.f;
            for (int n = lane; n < 1024; n += 32) s += P[r*P_LD + n];
#pragma unroll
            for (int o = 16; o; o >>= 1) s += __shfl_xor_sync(0xFFFFFFFFu, s, o);
            if (lane == 0) invl[r] = 1.f / s;
        }
    }
    __syncthreads();

    // ---- write normalized attn ----
    {
        const size_t base = ATTN_OFF + (((size_t)(b*16 + h))*1024 + m0)*1024;
        for (int e = tid; e < 32*1024; e += 256) {
            int i = e >> 10, n = e & 1023;
            out[base + (size_t)i*1024 + n] = P[i*P_LD + n] * invl[i];
        }
    }

    // ---- ctx = P @ V ----
    const int d0  = (tid & 15) << 2;   // 4 dims
    const int i0b = (tid >> 4) << 1;   // 2 rows
    float cacc[2][4];
#pragma unroll
    for (int ii = 0; ii < 2; ii++)
#pragma unroll
        for (int dd = 0; dd < 4; dd++) cacc[ii][dd] = 0.f;

    for (int c = 0; c < 8; c++) {
        const int n0 = c * 128;
        __syncthreads();  // previous chunk compute done before KV overwrite
        for (int e = tid; e < 128*64; e += 256) {
            int j = e >> 6, d = e & 63;
            KV[j*VS_LD + d] = g_v[((size_t)(b << 10) + n0 + j)*1024 + (h << 6) + d];
        }
        __syncthreads();
#pragma unroll 4
        for (int j = 0; j < 128; j++) {
            float p0 = P[i0b*P_LD + n0 + j];
            float p1 = P[(i0b + 1)*P_LD + n0 + j];
            float4 vv = *(const float4*)&KV[j*VS_LD + d0];
            cacc[0][0] += p0*vv.x; cacc[0][1] += p0*vv.y;
            cacc[0][2] += p0*vv.z; cacc[0][3] += p0*vv.w;
            cacc[1][0] += p1*vv.x; cacc[1][1] += p1*vv.y;
            cacc[1][2] += p1*vv.z; cacc[1][3] += p1*vv.w;
        }
    }
    __syncthreads();

    // ---- gate, store partial column means ----
#pragma unroll
    for (int ii = 0; ii < 2; ii++) {
        const int i = i0b + ii;
#pragma unroll
        for (int dd = 0; dd < 4; dd++) {
            const int d = d0 + dd;
            float g = g_gate[((size_t)(b << 10) + m0 + i)*1024 + (h << 6) + d];
            Cs[i*VS_LD + d] = cacc[ii][dd] * invl[i] * g;
        }
    }
    __syncthreads();
    if (tid < 64) {
        float s = 0.f;
#pragma unroll
        for (int i = 0; i < 32; i++) s += Cs[i*VS_LD + tid];
        g_part[(((b << 4) + h)*32 + mt)*64 + tid] = s * (1.f/1024.f);
    }
}

// ============================================================
// Kernel 4: z = colmean @ Wo + bo
// ============================================================
__global__ __launch_bounds__(256) void z_kernel(
    const float* __restrict__ Wo, const float* __restrict__ bo,
    float* __restrict__ out)
{
    __shared__ float cm[1024];
    const int b = blockIdx.x;
    const int o = blockIdx.y*256 + threadIdx.x;

    for (int c = threadIdx.x; c < 1024; c += 256) {
        int hh = c >> 6, d = c & 63;
        const float* pp = &g_part[(((b << 4) + hh)*32)*64 + d];
        float s = 0.f;
#pragma unroll
        for (int t = 0; t < 32; t++) s += pp[t*64];
        cm[c] = s;
    }
    __syncthreads();

    float acc = bo[o];
#pragma unroll 4
    for (int c = 0; c < 1024; c++) acc += cm[c] * Wo[(size_t)c*1024 + o];
    out[Z_OFF + (size_t)b*1024 + o] = acc;
}

// ============================================================
extern "C" void kernel_launch(void* const* d_in, const int* in_sizes, int n_in,
                              void* d_out, int out_size)
{
    const float* x   = (const float*)d_in[0];
    const float* Wq  = (const float*)d_in[1];
    const float* bq  = (const float*)d_in[2];
    const float* Wk  = (const float*)d_in[3];
    const float* bk  = (const float*)d_in[4];
    const float* Wv  = (const float*)d_in[5];
    const float* bv  = (const float*)d_in[6];
    const float* Wg  = (const float*)d_in[7];
    const float* bg  = (const float*)d_in[8];
    const float* Wo  = (const float*)d_in[9];
    const float* bo  = (const float*)d_in[10];
    const float* Wu1 = (const float*)d_in[11];
    const float* bu1 = (const float*)d_in[12];
    const float* Wu2 = (const float*)d_in[13];
    const float* bu2 = (const float*)d_in[14];
    float* out = (float*)d_out;

    proj_kernel<<<dim3(64, 34), 256>>>(x, Wq, bq, Wk, bk, Wv, bv, Wg, bg, Wu1, bu1);
    sigma_kernel<<<1024, 256>>>(Wu2, bu2, out);
    cudaFuncSetAttribute(attn_kernel, cudaFuncAttributeMaxDynamicSharedMemorySize,
                         ATTN_SMEM_BYTES);
    attn_kernel<<<dim3(32, 16, 8), 256, ATTN_SMEM_BYTES>>>(out);
    z_kernel<<<dim3(8, 4), 256>>>(Wo, bo, out);
}

// round 4
// speedup vs baseline: 4.1262x; 2.8287x over previous
#include <cuda_runtime.h>
#include <math.h>
#include <stdint.h>

#define B_  8
#define M_  1024
#define H_  1024
#define NH_ 16
#define HD_ 64
#define ROWS 8192
#define H1W 256

#define Z_OFF     ((size_t)0)
#define ATTN_OFF  ((size_t)8192)
#define SIGMA_OFF ((size_t)8192 + (size_t)B_*NH_*M_*M_)

// -------- scratch --------
__device__ float g_q[ROWS*H_];
__device__ float g_k[ROWS*H_];
__device__ float g_v[ROWS*H_];
__device__ float g_gate[ROWS*H_];
__device__ float g_h1[ROWS*H1W];
__device__ float g_sigma[ROWS];
__device__ float g_part[B_*NH_*32*HD_];

// -------- mma helpers --------
static __device__ __forceinline__ uint32_t f2tf32(float f){
    uint32_t r; asm("cvt.rna.tf32.f32 %0, %1;" : "=r"(r) : "f"(f)); return r;
}
static __device__ __forceinline__ void mma8(float* c, const uint32_t* a, const uint32_t* b){
    asm volatile("mma.sync.aligned.m16n8k8.row.col.f32.tf32.tf32.f32 "
        "{%0,%1,%2,%3}, {%4,%5,%6,%7}, {%8,%9}, {%0,%1,%2,%3};"
        : "+f"(c[0]), "+f"(c[1]), "+f"(c[2]), "+f"(c[3])
        : "r"(a[0]), "r"(a[1]), "r"(a[2]), "r"(a[3]), "r"(b[0]), "r"(b[1]));
}

// ============================================================
// Kernel 1: fused projection GEMM (tf32 tensor cores)
// C[8192,4352] = X @ [Wq|Wk|Wv|Wg|Wu1] + bias (+act)
// ============================================================
__global__ __launch_bounds__(256) void proj_kernel(
    const float* __restrict__ X,
    const float* __restrict__ Wq, const float* __restrict__ bq,
    const float* __restrict__ Wk, const float* __restrict__ bk,
    const float* __restrict__ Wv, const float* __restrict__ bv,
    const float* __restrict__ Wg, const float* __restrict__ bg,
    const float* __restrict__ Wu1, const float* __restrict__ bu1)
{
    __shared__ uint32_t Xs[128][20];   // [m][k], pad 20 -> conflict-free A frags
    __shared__ uint32_t Ws[16][136];   // [k][n], pad 136 -> conflict-free B frags

    const int rowt = blockIdx.x * 128;
    const int colt = blockIdx.y * 128;

    const float* W; const float* bias; float* out;
    int wld, outld, lcol, act;
    if (colt < 1024)      { W=Wq;  bias=bq;  out=g_q;    wld=1024; outld=1024; lcol=colt;      act=0; }
    else if (colt < 2048) { W=Wk;  bias=bk;  out=g_k;    wld=1024; outld=1024; lcol=colt-1024; act=0; }
    else if (colt < 3072) { W=Wv;  bias=bv;  out=g_v;    wld=1024; outld=1024; lcol=colt-2048; act=0; }
    else if (colt < 4096) { W=Wg;  bias=bg;  out=g_gate; wld=1024; outld=1024; lcol=colt-3072; act=1; }
    else                  { W=Wu1; bias=bu1; out=g_h1;   wld=256;  outld=256;  lcol=colt-4096; act=2; }

    const int tid = threadIdx.x;
    const int w   = tid >> 5, lane = tid & 31;
    const int g   = lane >> 2, t = lane & 3;
    const int m0w = (w & 3) * 32;
    const int n0w = (w >> 2) * 64;

    float acc[2][8][4];
#pragma unroll
    for (int i = 0; i < 2; i++)
#pragma unroll
        for (int j = 0; j < 8; j++)
#pragma unroll
            for (int r = 0; r < 4; r++) acc[i][j][r] = 0.f;

    for (int k0 = 0; k0 < 1024; k0 += 16) {
#pragma unroll
        for (int it = 0; it < 2; it++) {
            int i = tid + it*256;            // 0..511
            int r = i >> 2, kq = (i & 3) << 2;
            float4 v = *(const float4*)&X[(size_t)(rowt + r)*1024 + k0 + kq];
            Xs[r][kq+0]=f2tf32(v.x); Xs[r][kq+1]=f2tf32(v.y);
            Xs[r][kq+2]=f2tf32(v.z); Xs[r][kq+3]=f2tf32(v.w);
        }
#pragma unroll
        for (int it = 0; it < 2; it++) {
            int i = tid + it*256;
            int kr = i >> 5, c4 = (i & 31) << 2;
            float4 v = *(const float4*)&W[(size_t)(k0 + kr)*wld + lcol + c4];
            Ws[kr][c4+0]=f2tf32(v.x); Ws[kr][c4+1]=f2tf32(v.y);
            Ws[kr][c4+2]=f2tf32(v.z); Ws[kr][c4+3]=f2tf32(v.w);
        }
        __syncthreads();
#pragma unroll
        for (int ks = 0; ks < 16; ks += 8) {
            uint32_t a[2][4];
#pragma unroll
            for (int i = 0; i < 2; i++) {
                a[i][0] = Xs[m0w + i*16 + g    ][ks + t];
                a[i][1] = Xs[m0w + i*16 + g + 8][ks + t];
                a[i][2] = Xs[m0w + i*16 + g    ][ks + t + 4];
                a[i][3] = Xs[m0w + i*16 + g + 8][ks + t + 4];
            }
#pragma unroll
            for (int j = 0; j < 8; j++) {
                uint32_t b[2];
                b[0] = Ws[ks + t    ][n0w + j*8 + g];
                b[1] = Ws[ks + t + 4][n0w + j*8 + g];
                mma8(acc[0][j], a[0], b);
                mma8(acc[1][j], a[1], b);
            }
        }
        __syncthreads();
    }

#pragma unroll
    for (int i = 0; i < 2; i++) {
#pragma unroll
        for (int j = 0; j < 8; j++) {
            int gc = lcol + n0w + j*8 + 2*t;
            float b0 = bias[gc], b1 = bias[gc + 1];
            float c0 = acc[i][j][0] + b0, c1 = acc[i][j][1] + b1;
            float c2 = acc[i][j][2] + b0, c3 = acc[i][j][3] + b1;
            if (act == 1) {
                c0 = 1.f/(1.f+__expf(-c0)); c1 = 1.f/(1.f+__expf(-c1));
                c2 = 1.f/(1.f+__expf(-c2)); c3 = 1.f/(1.f+__expf(-c3));
            } else if (act == 2) {
                c0 = fmaxf(c0,0.f); c1 = fmaxf(c1,0.f);
                c2 = fmaxf(c2,0.f); c3 = fmaxf(c3,0.f);
            }
            int gr = rowt + m0w + i*16 + g;
            *(float2*)&out[(size_t)gr*outld + gc]       = make_float2(c0, c1);
            *(float2*)&out[(size_t)(gr+8)*outld + gc]   = make_float2(c2, c3);
        }
    }
}

// ============================================================
// Kernel 2: sigma
// ============================================================
__global__ __launch_bounds__(256) void sigma_kernel(
    const float* __restrict__ Wu2, const float* __restrict__ bu2,
    float* __restrict__ out)
{
    const int tid = threadIdx.x, w = tid >> 5, lane = tid & 31;
    const int row = blockIdx.x * 8 + w;
    const float* hr = &g_h1[(size_t)row * H1W];
    float s = 0.f;
#pragma unroll
    for (int j = lane; j < H1W; j += 32) s += hr[j] * Wu2[j];
#pragma unroll
    for (int o = 16; o; o >>= 1) s += __shfl_xor_sync(0xFFFFFFFFu, s, o);
    if (lane == 0) {
        float v  = s + bu2[0];
        float sp = (v > 15.f) ? v : log1pf(__expf(v));
        float sg = sp + 1e-6f;
        g_sigma[row] = sg;
        out[SIGMA_OFF + row] = sg;
    }
}

// ============================================================
// Kernel 3: attention (tf32 mma for QK^T and P@V)
// ============================================================
#define SM_P    0                      // fp32 [32][1028]
#define SM_QS   32896                  // tf32 [32][68]
#define SM_KV   35072                  // tf32 K:[128][68] / V:[128][72]
#define SM_ISN  44288                  // [1024]
#define SM_SCL  45312                  // [32]
#define SM_INVL 45344                  // [32]
#define SM_CS   45376                  // fp32 [32][68]
#define SM_TOT  47552
#define ATTN_SMEM_BYTES (SM_TOT*4)

__global__ __launch_bounds__(256) void attn_kernel(float* __restrict__ out)
{
    extern __shared__ float sm[];
    float*    P    = sm + SM_P;
    uint32_t* Qs   = (uint32_t*)(sm + SM_QS);
    uint32_t* KV   = (uint32_t*)(sm + SM_KV);
    float*    isn  = sm + SM_ISN;
    float*    scl  = sm + SM_SCL;
    float*    invl = sm + SM_INVL;
    float*    Cs   = sm + SM_CS;

    const int mt = blockIdx.x, h = blockIdx.y, b = blockIdx.z;
    const int m0 = mt * 32;
    const int tid = threadIdx.x;
    const int w = tid >> 5, lane = tid & 31;
    const int g = lane >> 2, t = lane & 3;

    for (int n = tid; n < 1024; n += 256) isn[n] = 1.f / g_sigma[(b << 10) + n];
    if (tid < 32) scl[tid] = 0.125f / g_sigma[(b << 10) + m0 + tid];

    // Q tile -> Qs[m][k] (tf32)
#pragma unroll
    for (int it = 0; it < 2; it++) {
        int i = tid + it*256;           // 0..511
        int r = i >> 4, c4 = (i & 15) << 2;
        float4 v = *(const float4*)&g_q[((size_t)(b << 10) + m0 + r)*1024 + (h << 6) + c4];
        Qs[r*68 + c4+0]=f2tf32(v.x); Qs[r*68 + c4+1]=f2tf32(v.y);
        Qs[r*68 + c4+2]=f2tf32(v.z); Qs[r*68 + c4+3]=f2tf32(v.w);
    }

    // ---- QK^T: per 128-col chunk, warp w covers 16 cols ----
    for (int c = 0; c < 8; c++) {
        const int n0c = c * 128;
        __syncthreads();
#pragma unroll
        for (int it = 0; it < 8; it++) {
            int i = tid + it*256;       // 0..2047
            int r = i >> 4, c4 = (i & 15) << 2;
            float4 v = *(const float4*)&g_k[((size_t)(b << 10) + n0c + r)*1024 + (h << 6) + c4];
            KV[r*68 + c4+0]=f2tf32(v.x); KV[r*68 + c4+1]=f2tf32(v.y);
            KV[r*68 + c4+2]=f2tf32(v.z); KV[r*68 + c4+3]=f2tf32(v.w);
        }
        __syncthreads();

        float acc[2][2][4];
#pragma unroll
        for (int i = 0; i < 2; i++)
#pragma unroll
            for (int j = 0; j < 2; j++)
#pragma unroll
                for (int r = 0; r < 4; r++) acc[i][j][r] = 0.f;

#pragma unroll
        for (int ks = 0; ks < 64; ks += 8) {
            uint32_t a[2][4];
#pragma unroll
            for (int i = 0; i < 2; i++) {
                a[i][0] = Qs[(i*16 + g    )*68 + ks + t];
                a[i][1] = Qs[(i*16 + g + 8)*68 + ks + t];
                a[i][2] = Qs[(i*16 + g    )*68 + ks + t + 4];
                a[i][3] = Qs[(i*16 + g + 8)*68 + ks + t + 4];
            }
#pragma unroll
            for (int j = 0; j < 2; j++) {
                uint32_t bb[2];
                bb[0] = KV[(w*16 + j*8 + g)*68 + ks + t];
                bb[1] = KV[(w*16 + j*8 + g)*68 + ks + t + 4];
                mma8(acc[0][j], a[0], bb);
                mma8(acc[1][j], a[1], bb);
            }
        }
#pragma unroll
        for (int i = 0; i < 2; i++) {
            int r0 = i*16 + g, r1 = r0 + 8;
#pragma unroll
            for (int j = 0; j < 2; j++) {
                int nl = w*16 + j*8 + 2*t;
                P[r0*1028 + n0c + nl    ] = __expf(acc[i][j][0]*scl[r0]*isn[n0c+nl]);
                P[r0*1028 + n0c + nl + 1] = __expf(acc[i][j][1]*scl[r0]*isn[n0c+nl+1]);
                P[r1*1028 + n0c + nl    ] = __expf(acc[i][j][2]*scl[r1]*isn[n0c+nl]);
                P[r1*1028 + n0c + nl + 1] = __expf(acc[i][j][3]*scl[r1]*isn[n0c+nl+1]);
            }
        }
    }
    __syncthreads();

    // ---- row sums ----
#pragma unroll
    for (int r = w*4; r < w*4 + 4; r++) {
        float s = 0.f;
        for (int n = lane; n < 1024; n += 32) s += P[r*1028 + n];
#pragma unroll
        for (int o = 16; o; o >>= 1) s += __shfl_xor_sync(0xFFFFFFFFu, s, o);
        if (lane == 0) invl[r] = 1.f / s;
    }
    __syncthreads();

    // ---- normalized attn write (float4) ----
    {
        const size_t base = ATTN_OFF + (((size_t)(b*16 + h))*1024 + m0)*1024;
        for (int e = tid; e < 32*256; e += 256) {
            int i = e >> 8, n4 = (e & 255) << 2;
            float4 p = *(float4*)&P[i*1028 + n4];
            float iv = invl[i];
            p.x *= iv; p.y *= iv; p.z *= iv; p.w *= iv;
            *(float4*)&out[base + (size_t)i*1024 + n4] = p;
        }
    }

    // ---- ctx = P @ V : warp w covers d-slice w*8 ----
    float cacc[2][4];
#pragma unroll
    for (int i = 0; i < 2; i++)
#pragma unroll
        for (int r = 0; r < 4; r++) cacc[i][r] = 0.f;

    for (int c = 0; c < 8; c++) {
        const int n0c = c * 128;
        __syncthreads();
#pragma unroll
        for (int it = 0; it < 8; it++) {
            int i = tid + it*256;
            int r = i >> 4, c4 = (i & 15) << 2;
            float4 v = *(const float4*)&g_v[((size_t)(b << 10) + n0c + r)*1024 + (h << 6) + c4];
            uint4 u; u.x=f2tf32(v.x); u.y=f2tf32(v.y); u.z=f2tf32(v.z); u.w=f2tf32(v.w);
            *(uint4*)&KV[r*72 + c4] = u;
        }
        __syncthreads();
#pragma unroll
        for (int ks = 0; ks < 128; ks += 8) {
            uint32_t a[2][4];
#pragma unroll
            for (int i = 0; i < 2; i++) {
                a[i][0] = f2tf32(P[(i*16 + g    )*1028 + n0c + ks + t]);
                a[i][1] = f2tf32(P[(i*16 + g + 8)*1028 + n0c + ks + t]);
                a[i][2] = f2tf32(P[(i*16 + g    )*1028 + n0c + ks + t + 4]);
                a[i][3] = f2tf32(P[(i*16 + g + 8)*1028 + n0c + ks + t + 4]);
            }
            uint32_t bb[2];
            bb[0] = KV[(ks + t    )*72 + w*8 + g];
            bb[1] = KV[(ks + t + 4)*72 + w*8 + g];
            mma8(cacc[0], a[0], bb);
            mma8(cacc[1], a[1], bb);
        }
    }
    __syncthreads();

    // ---- gate + invl, partial col means ----
#pragma unroll
    for (int i = 0; i < 2; i++) {
        int r0 = i*16 + g, r1 = r0 + 8;
        int d = w*8 + 2*t;
        float g0 = g_gate[((size_t)(b << 10) + m0 + r0)*1024 + (h << 6) + d];
        float g1 = g_gate[((size_t)(b << 10) + m0 + r0)*1024 + (h << 6) + d + 1];
        float g2 = g_gate[((size_t)(b << 10) + m0 + r1)*1024 + (h << 6) + d];
        float g3 = g_gate[((size_t)(b << 10) + m0 + r1)*1024 + (h << 6) + d + 1];
        Cs[r0*68 + d    ] = cacc[i][0] * invl[r0] * g0;
        Cs[r0*68 + d + 1] = cacc[i][1] * invl[r0] * g1;
        Cs[r1*68 + d    ] = cacc[i][2] * invl[r1] * g2;
        Cs[r1*68 + d + 1] = cacc[i][3] * invl[r1] * g3;
    }
    __syncthreads();
    if (tid < 64) {
        float s = 0.f;
#pragma unroll
        for (int i = 0; i < 32; i++) s += Cs[i*68 + tid];
        g_part[(((b << 4) + h)*32 + mt)*64 + tid] = s * (1.f/1024.f);
    }
}

// ============================================================
// Kernel 4: z = colmean @ Wo + bo  (k-split, grid 8x16)
// ============================================================
__global__ __launch_bounds__(256) void z_kernel(
    const float* __restrict__ Wo, const float* __restrict__ bo,
    float* __restrict__ out)
{
    __shared__ float cm[1024];
    __shared__ float red[4][64];
    const int b = blockIdx.x, oc = blockIdx.y;

    for (int c = threadIdx.x; c < 1024; c += 256) {
        int hh = c >> 6, d = c & 63;
        const float* pp = &g_part[(size_t)(((b << 4) + hh)*32)*64 + d];
        float s = 0.f;
#pragma unroll
        for (int tt = 0; tt < 32; tt++) s += pp[tt*64];
        cm[c] = s;
    }
    __syncthreads();

    const int oi = threadIdx.x & 63, ks = threadIdx.x >> 6;
    const int o  = oc*64 + oi;
    float s = 0.f;
#pragma unroll 4
    for (int k = ks*256; k < ks*256 + 256; k++) s += cm[k] * Wo[(size_t)k*1024 + o];
    red[ks][oi] = s;
    __syncthreads();
    if (threadIdx.x < 64) {
        float r = red[0][threadIdx.x] + red[1][threadIdx.x]
                + red[2][threadIdx.x] + red[3][threadIdx.x] + bo[oc*64 + threadIdx.x];
        out[Z_OFF + (size_t)b*1024 + oc*64 + threadIdx.x] = r;
    }
}

// ============================================================
extern "C" void kernel_launch(void* const* d_in, const int* in_sizes, int n_in,
                              void* d_out, int out_size)
{
    const float* x   = (const float*)d_in[0];
    const float* Wq  = (const float*)d_in[1];
    const float* bq  = (const float*)d_in[2];
    const float* Wk  = (const float*)d_in[3];
    const float* bk  = (const float*)d_in[4];
    const float* Wv  = (const float*)d_in[5];
    const float* bv  = (const float*)d_in[6];
    const float* Wg  = (const float*)d_in[7];
    const float* bg  = (const float*)d_in[8];
    const float* Wo  = (const float*)d_in[9];
    const float* bo  = (const float*)d_in[10];
    const float* Wu1 = (const float*)d_in[11];
    const float* bu1 = (const float*)d_in[12];
    const float* Wu2 = (const float*)d_in[13];
    const float* bu2 = (const float*)d_in[14];
    float* out = (float*)d_out;

    proj_kernel<<<dim3(64, 34), 256>>>(x, Wq, bq, Wk, bk, Wv, bv, Wg, bg, Wu1, bu1);
    sigma_kernel<<<1024, 256>>>(Wu2, bu2, out);
    cudaFuncSetAttribute(attn_kernel, cudaFuncAttributeMaxDynamicSharedMemorySize,
                         ATTN_SMEM_BYTES);
    attn_kernel<<<dim3(32, 16, 8), 256, ATTN_SMEM_BYTES>>>(out);
    z_kernel<<<dim3(8, 16), 256>>>(Wo, bo, out);
}